// round 2
// baseline (speedup 1.0000x reference)
#include <cuda_runtime.h>
#include <stdint.h>

#define NN   8192
#define KSEL 64
#define NT   256
#define EPT  32          // elements per thread (NN / NT)
#define CAP  2048        // candidate buffer capacity

// Bit-exact replica of XLA's EmitFastTanh (f32, with_fma=true variant):
//   clamp to +-7.99881172180175781, Eigen rational 13/6 via FMA Horner,
//   IEEE div, |x| < 0.0004 passthrough.
__device__ __forceinline__ float xla_tanh(float x) {
    const float pc = 7.99881172180175781f;
    float xc = fminf(fmaxf(x, -pc), pc);
    float x2 = __fmul_rn(xc, xc);
    float num = -2.76076847742355e-16f;
    num = __fmaf_rn(x2, num, 2.00018790482477e-13f);
    num = __fmaf_rn(x2, num, -8.60467152213735e-11f);
    num = __fmaf_rn(x2, num, 5.12229709037114e-08f);
    num = __fmaf_rn(x2, num, 1.48572235717979e-05f);
    num = __fmaf_rn(x2, num, 6.37261928875436e-04f);
    num = __fmaf_rn(x2, num, 4.89352455891786e-03f);
    num = __fmul_rn(xc, num);
    float den = 1.19825839466702e-06f;
    den = __fmaf_rn(x2, den, 1.18534705686654e-04f);
    den = __fmaf_rn(x2, den, 2.26843463243900e-03f);
    den = __fmaf_rn(x2, den, 4.89352518554385e-03f);
    float r = __fdiv_rn(num, den);
    return (fabsf(x) < 0.0004f) ? x : r;
}

__global__ __launch_bounds__(NT) void topk_tanh_kernel(
    const float* __restrict__ A, float* __restrict__ out)
{
    __shared__ float    s_adj[NN];      // 32 KB: signed adj = tanh(3a)
    __shared__ uint32_t s_cand[CAP];    // 8 KB: candidate keys / equal idx (reused)
    __shared__ uint32_t s_hist[256];
    __shared__ uint32_t s_cnt;
    __shared__ uint32_t s_bc[2];

    const int t    = threadIdx.x;
    const int lane = t & 31;
    const int row  = blockIdx.x;

    const float4* rp = (const float4*)(A + (size_t)row * NN);
    float4* s4 = (float4*)s_adj;

    // ---- Phase 1: load row, compute adj, stash in smem --------------------
#pragma unroll
    for (int i = 0; i < EPT / 4; i++) {
        float4 v = rp[i * NT + t];
        float4 w;
        w.x = xla_tanh(3.0f * v.x);
        w.y = xla_tanh(3.0f * v.y);
        w.z = xla_tanh(3.0f * v.z);
        w.w = xla_tanh(3.0f * v.w);
        s4[i * NT + t] = w;
    }
    __syncthreads();

    // ---- Phase 2: candidate compaction (keys > thr in |adj| space) --------
    float thr = 0.9999990f;      // expected ~128 candidates/row
    uint32_t count = 0;
    bool use_row = false;
    for (int iter = 0; iter < 64; iter++) {
        if (t == 0) s_cnt = 0;
        __syncthreads();
        const uint32_t tk = __float_as_uint(thr);
#pragma unroll
        for (int i = 0; i < EPT; i++) {
            uint32_t key = __float_as_uint(s_adj[i * NT + t]) & 0x7fffffffu;
            bool p = (key > tk);
            unsigned m = __ballot_sync(0xffffffffu, p);
            unsigned base = 0;
            if (lane == 0) base = atomicAdd(&s_cnt, (unsigned)__popc(m));
            base = __shfl_sync(0xffffffffu, base, 0);
            if (p) {
                unsigned pos = base + __popc(m & ((1u << lane) - 1u));
                if (pos < CAP) s_cand[pos] = key;
            }
        }
        __syncthreads();
        count = s_cnt;
        if (count >= KSEL) { use_row = (count > CAP); break; }
        if (thr <= 0.0f)   { use_row = true; break; }   // <K positive keys
        thr = fmaxf(__fmaf_rn(2.0f, thr, -1.0f), 0.0f); // double the gap to 1
        __syncthreads();
    }
    if (count < KSEL) use_row = true;

    // ---- Phase 3: 4x8-bit radix select for the K-th largest key -----------
    uint32_t prefix = 0, pmask = 0, need = KSEL;
    for (int shift = 24; shift >= 0; shift -= 8) {
        s_hist[t] = 0;   // NT == 256
        __syncthreads();
        if (use_row) {
#pragma unroll
            for (int i = 0; i < EPT; i++) {
                uint32_t key = __float_as_uint(s_adj[i * NT + t]) & 0x7fffffffu;
                if ((key & pmask) == prefix)
                    atomicAdd(&s_hist[(key >> shift) & 255u], 1u);
            }
        } else {
            for (uint32_t i = t; i < count; i += NT) {
                uint32_t key = s_cand[i];
                if ((key & pmask) == prefix)
                    atomicAdd(&s_hist[(key >> shift) & 255u], 1u);
            }
        }
        __syncthreads();
        if (t < 32) {
            uint32_t s = 0;
#pragma unroll
            for (int j = 0; j < 8; j++) s += s_hist[t * 8 + j];
            uint32_t suf = s;
#pragma unroll
            for (int d = 1; d < 32; d <<= 1) {
                uint32_t v = __shfl_down_sync(0xffffffffu, suf, d);
                if (t + d < 32) suf += v;
            }
            uint32_t sufnext = __shfl_down_sync(0xffffffffu, suf, 1);
            if (t == 31) sufnext = 0u;
            if (suf >= need && sufnext < need) {   // exactly one lane
                uint32_t cum = sufnext, b = 0, above = 0;
                for (int j = 7; j >= 0; j--) {
                    uint32_t h = s_hist[t * 8 + j];
                    if (cum + h >= need) { b = (uint32_t)(t * 8 + j); above = cum; break; }
                    cum += h;
                }
                s_bc[0] = prefix | (b << shift);
                s_bc[1] = need - above;
            }
        }
        __syncthreads();
        prefix = s_bc[0];
        need   = s_bc[1];
        pmask |= (0xffu << shift);
        __syncthreads();
    }
    const uint32_t T = prefix;   // K-th largest key
    const uint32_t E = need;     // how many equals-to-T to take (lowest index)

    // ---- Phase 4: collect indices of equals, resolve tie-break ------------
    if (t == 0) s_cnt = 0;
    __syncthreads();
#pragma unroll
    for (int i = 0; i < EPT; i++) {
        int idx = i * NT + t;
        uint32_t key = __float_as_uint(s_adj[idx]) & 0x7fffffffu;
        bool p = (key == T);
        unsigned m = __ballot_sync(0xffffffffu, p);
        unsigned base = 0;
        if (lane == 0) base = atomicAdd(&s_cnt, (unsigned)__popc(m));
        base = __shfl_sync(0xffffffffu, base, 0);
        if (p) {
            unsigned pos = base + __popc(m & ((1u << lane) - 1u));
            if (pos < CAP) s_cand[pos] = (uint32_t)idx;
        }
    }
    __syncthreads();
    const uint32_t Q = s_cnt;
    uint32_t mSel = NN;                    // Q == E: take all equals
    if (Q > E) {                           // binary search smallest m: cnt(idx<m) >= E
        const bool qfit = (Q <= CAP);
        uint32_t lo = 0, hi = NN;
        while (hi - lo > 1u) {
            uint32_t mid = (lo + hi) >> 1;
            if (t == 0) s_cnt = 0;
            __syncthreads();
            unsigned lc = 0;
            if (qfit) {
                for (uint32_t i = t; i < Q; i += NT) lc += (s_cand[i] < mid);
            } else {
#pragma unroll
                for (int i = 0; i < EPT; i++) {
                    int idx = i * NT + t;
                    uint32_t key = __float_as_uint(s_adj[idx]) & 0x7fffffffu;
                    lc += (key == T && (uint32_t)idx < mid);
                }
            }
            unsigned ws = __reduce_add_sync(0xffffffffu, lc);
            if (lane == 0) atomicAdd(&s_cnt, ws);
            __syncthreads();
            uint32_t cnt = s_cnt;
            if (cnt >= E) hi = mid; else lo = mid;
            __syncthreads();
        }
        mSel = hi;
    }
    __syncthreads();

    // ---- Phase 5: streamed masked output -----------------------------------
    float4* op = (float4*)(out + (size_t)row * NN);
#pragma unroll
    for (int i = 0; i < EPT / 4; i++) {
        int b4 = i * NT + t;
        float4 v = s4[b4];
        int idx0 = b4 * 4;
        float4 w;
        uint32_t kx = __float_as_uint(v.x) & 0x7fffffffu;
        uint32_t ky = __float_as_uint(v.y) & 0x7fffffffu;
        uint32_t kz = __float_as_uint(v.z) & 0x7fffffffu;
        uint32_t kw = __float_as_uint(v.w) & 0x7fffffffu;
        w.x = (kx > T || (kx == T && (uint32_t)(idx0 + 0) < mSel)) ? v.x : 0.0f;
        w.y = (ky > T || (ky == T && (uint32_t)(idx0 + 1) < mSel)) ? v.y : 0.0f;
        w.z = (kz > T || (kz == T && (uint32_t)(idx0 + 2) < mSel)) ? v.z : 0.0f;
        w.w = (kw > T || (kw == T && (uint32_t)(idx0 + 3) < mSel)) ? v.w : 0.0f;
        op[b4] = w;
    }
}

extern "C" void kernel_launch(void* const* d_in, const int* in_sizes, int n_in,
                              void* d_out, int out_size)
{
    // inputs: idx (int64, 8192) first, A (f32, 8192*8192) second — pick by size
    const float* A = nullptr;
    for (int i = 0; i < n_in; i++)
        if (in_sizes[i] == NN * NN) A = (const float*)d_in[i];
    float* out = (float*)d_out;
    topk_tanh_kernel<<<NN, NT>>>(A, out);
}

// round 3
// speedup vs baseline: 2.2366x; 2.2366x over previous
#include <cuda_runtime.h>
#include <stdint.h>

#define NN   8192
#define KSEL 64
#define NT   256
#define EPT  32          // elements per thread (NN / NT)
#define CAP  640         // candidate buffer capacity (mean ~128, sigma ~11)

// Bit-exact replica of XLA's EmitFastTanh (f32, with_fma=true variant).
__device__ __forceinline__ float xla_tanh(float x) {
    const float pc = 7.99881172180175781f;
    float xc = fminf(fmaxf(x, -pc), pc);
    float x2 = __fmul_rn(xc, xc);
    float num = -2.76076847742355e-16f;
    num = __fmaf_rn(x2, num, 2.00018790482477e-13f);
    num = __fmaf_rn(x2, num, -8.60467152213735e-11f);
    num = __fmaf_rn(x2, num, 5.12229709037114e-08f);
    num = __fmaf_rn(x2, num, 1.48572235717979e-05f);
    num = __fmaf_rn(x2, num, 6.37261928875436e-04f);
    num = __fmaf_rn(x2, num, 4.89352455891786e-03f);
    num = __fmul_rn(xc, num);
    float den = 1.19825839466702e-06f;
    den = __fmaf_rn(x2, den, 1.18534705686654e-04f);
    den = __fmaf_rn(x2, den, 2.26843463243900e-03f);
    den = __fmaf_rn(x2, den, 4.89352518554385e-03f);
    float r = __fdiv_rn(num, den);
    return (fabsf(x) < 0.0004f) ? x : r;
}

// packed candidate: (key << 13) | (8191 - idx). K-th largest packed value is
// the exact top_k threshold with lowest-index tie-break (larger packed =
// larger key, or equal key & smaller idx).
__device__ __forceinline__ unsigned long long pack_cand(uint32_t key, int idx) {
    return ((unsigned long long)key << 13) | (uint32_t)(8191 - idx);
}

__global__ __launch_bounds__(NT, 5) void topk_tanh_kernel(
    const float* __restrict__ A, float* __restrict__ out)
{
    __shared__ float s_adj[NN];                     // 32 KB
    __shared__ unsigned long long s_cand[CAP];      // 5 KB
    __shared__ unsigned long long s_P;
    __shared__ uint32_t s_cnt;

    const int t   = threadIdx.x;
    const int row = blockIdx.x;

    const float4* rp = (const float4*)(A + (size_t)row * NN);
    float4* s4 = (float4*)s_adj;

    if (t == 0) s_cnt = 0;
    __syncthreads();

    // ---- Phase 1: load row, compute adj, stash in smem, fused candidate push
    const uint32_t tk0 = __float_as_uint(0.9999990f);   // ~128 cands expected
#pragma unroll
    for (int i = 0; i < EPT / 4; i++) {
        float4 v = rp[i * NT + t];
        float4 w;
        w.x = xla_tanh(3.0f * v.x);
        w.y = xla_tanh(3.0f * v.y);
        w.z = xla_tanh(3.0f * v.z);
        w.w = xla_tanh(3.0f * v.w);
        s4[i * NT + t] = w;
        const int idx0 = (i * NT + t) * 4;
        uint32_t k0 = __float_as_uint(w.x) & 0x7fffffffu;
        uint32_t k1 = __float_as_uint(w.y) & 0x7fffffffu;
        uint32_t k2 = __float_as_uint(w.z) & 0x7fffffffu;
        uint32_t k3 = __float_as_uint(w.w) & 0x7fffffffu;
        if (k0 > tk0) { uint32_t p = atomicAdd(&s_cnt, 1u); if (p < CAP) s_cand[p] = pack_cand(k0, idx0 + 0); }
        if (k1 > tk0) { uint32_t p = atomicAdd(&s_cnt, 1u); if (p < CAP) s_cand[p] = pack_cand(k1, idx0 + 1); }
        if (k2 > tk0) { uint32_t p = atomicAdd(&s_cnt, 1u); if (p < CAP) s_cand[p] = pack_cand(k2, idx0 + 2); }
        if (k3 > tk0) { uint32_t p = atomicAdd(&s_cnt, 1u); if (p < CAP) s_cand[p] = pack_cand(k3, idx0 + 3); }
    }
    __syncthreads();
    uint32_t cnt = s_cnt;

    // ---- Rare fallback: bisect integer key-threshold until K <= cnt <= CAP
    if (cnt < KSEL || cnt > CAP) {
        uint32_t lo = 0u, hi = 0x7f800000u;
        if (cnt < KSEL) hi = tk0; else lo = tk0;
        for (int iter = 0; iter < 40; iter++) {
            uint32_t tk = lo + ((hi - lo) >> 1);
            __syncthreads();
            if (t == 0) s_cnt = 0;
            __syncthreads();
            for (int j = t; j < NN; j += NT) {
                uint32_t key = __float_as_uint(s_adj[j]) & 0x7fffffffu;
                if (key > tk) {
                    uint32_t p = atomicAdd(&s_cnt, 1u);
                    if (p < CAP) s_cand[p] = pack_cand(key, j);
                }
            }
            __syncthreads();
            cnt = s_cnt;
            if (cnt >= KSEL && cnt <= CAP) break;
            if (cnt < KSEL) hi = tk; else lo = tk;
            if (hi - lo <= 1u) break;
        }
    }

    // ---- Phase 2: exact K-th largest packed candidate via rank counting
    if (cnt >= KSEL) {
        uint32_t c = (cnt > CAP) ? CAP : cnt;   // unreachable safety clamp
        for (uint32_t i = t; i < c; i += NT) {
            unsigned long long me = s_cand[i];
            uint32_t r = 0;
            for (uint32_t j = 0; j < c; j++) r += (s_cand[j] > me);
            if (r == KSEL - 1) s_P = me;        // unique: packed values distinct
        }
    } else if (t == 0) {
        // fewer than K nonzero keys: select all nonzero (extra selected zeros
        // in the reference output 0 either way)
        s_P = ((unsigned long long)1 << 13);
    }
    __syncthreads();
    const unsigned long long P = s_P;
    const uint32_t Tkey   = (uint32_t)(P >> 13);
    const uint32_t idxMax = 8191u - (uint32_t)(P & 8191u);

    // ---- Phase 3: streamed masked output
    float4* op = (float4*)(out + (size_t)row * NN);
#pragma unroll
    for (int i = 0; i < EPT / 4; i++) {
        const int b4 = i * NT + t;
        float4 v = s4[b4];
        const uint32_t idx0 = (uint32_t)(b4 * 4);
        uint32_t kx = __float_as_uint(v.x) & 0x7fffffffu;
        uint32_t ky = __float_as_uint(v.y) & 0x7fffffffu;
        uint32_t kz = __float_as_uint(v.z) & 0x7fffffffu;
        uint32_t kw = __float_as_uint(v.w) & 0x7fffffffu;
        float4 w;
        w.x = (kx > Tkey || (kx == Tkey && idx0 + 0u <= idxMax)) ? v.x : 0.0f;
        w.y = (ky > Tkey || (ky == Tkey && idx0 + 1u <= idxMax)) ? v.y : 0.0f;
        w.z = (kz > Tkey || (kz == Tkey && idx0 + 2u <= idxMax)) ? v.z : 0.0f;
        w.w = (kw > Tkey || (kw == Tkey && idx0 + 3u <= idxMax)) ? v.w : 0.0f;
        op[b4] = w;
    }
}

extern "C" void kernel_launch(void* const* d_in, const int* in_sizes, int n_in,
                              void* d_out, int out_size)
{
    const float* A = nullptr;
    for (int i = 0; i < n_in; i++)
        if (in_sizes[i] == NN * NN) A = (const float*)d_in[i];
    float* out = (float*)d_out;
    topk_tanh_kernel<<<NN, NT>>>(A, out);
}